// round 1
// baseline (speedup 1.0000x reference)
#include <cuda_runtime.h>
#include <math.h>

#define BN   64
#define FINN 96
#define FOUTN 128
#define OPDN 48
#define SUP_LD 129   // padded stride for support / whk / wa
#define SC_LD  68    // padded stride for scores/attn (float4-aligned)
#define EPSV 1e-5f
#define SLOPEV 0.01f

// shared layout (floats):
//  sh_h    : 64*96   = 6144
//  sh_buf  : 96*128  = 12288   (W -> Wk -> Wop_d|Wop_g -> wa[64*129])
//  sh_adj  : 64*64   = 4096
//  sh_op   : 64*48   = 3072
//  sh_sup  : 64*129  = 8256    (support -> dense, in place)
//  sh_whk  : 64*129  = 8256    (Whk -> hp, in place)
//  sh_sc   : 64*68   = 4352    (alpha -> attn, in place)
//  sh_mu   : 64
//  sh_rs   : 64
#define SMEM_FLOATS (6144 + 12288 + 4096 + 3072 + 8256 + 8256 + 4352 + 64 + 64)

__global__ void __launch_bounds__(256, 1)
gin_fused_kernel(const float* __restrict__ g_h, const float* __restrict__ g_adj,
                 const float* __restrict__ g_op,
                 const float* __restrict__ g_W,  const float* __restrict__ g_b,
                 const float* __restrict__ g_Wopd, const float* __restrict__ g_bopd,
                 const float* __restrict__ g_Wk, const float* __restrict__ g_aw,
                 const float* __restrict__ g_Wopg, const float* __restrict__ g_bopg,
                 const float* __restrict__ g_gamma, const float* __restrict__ g_beta,
                 float* __restrict__ g_out)
{
    extern __shared__ float smem[];
    float* sh_h   = smem;
    float* sh_buf = sh_h + BN * FINN;
    float* sh_adj = sh_buf + FINN * FOUTN;
    float* sh_op  = sh_adj + BN * BN;
    float* sh_sup = sh_op + BN * OPDN;
    float* sh_whk = sh_sup + BN * SUP_LD;
    float* sh_sc  = sh_whk + BN * SUP_LD;
    float* sh_mu  = sh_sc + BN * SC_LD;
    float* sh_rs  = sh_mu + BN;

    const int tid = threadIdx.x;
    const int bb  = blockIdx.x;

    const float* hB   = g_h   + (size_t)bb * BN * FINN;
    const float* adjB = g_adj + (size_t)bb * BN * BN;
    const float* opB  = g_op  + (size_t)bb * BN * OPDN;
    float*       outB = g_out + (size_t)bb * BN * FOUTN;

    // ---- cooperative loads (float4, all sizes divisible by 4) ----
    {
        const float4* s; float4* d; int n4;
        s = (const float4*)hB;   d = (float4*)sh_h;   n4 = BN*FINN/4;
        for (int i = tid; i < n4; i += 256) d[i] = s[i];
        s = (const float4*)g_W;  d = (float4*)sh_buf; n4 = FINN*FOUTN/4;
        for (int i = tid; i < n4; i += 256) d[i] = s[i];
        s = (const float4*)adjB; d = (float4*)sh_adj; n4 = BN*BN/4;
        for (int i = tid; i < n4; i += 256) d[i] = s[i];
        s = (const float4*)opB;  d = (float4*)sh_op;  n4 = BN*OPDN/4;
        for (int i = tid; i < n4; i += 256) d[i] = s[i];
    }
    __syncthreads();

    const int col = tid & 127;
    const int rb  = tid >> 7;   // 0 or 1; uniform within each warp

    // ---- support = h @ W  -> sh_sup ----
    {
        float acc[32];
        #pragma unroll
        for (int i = 0; i < 32; i++) acc[i] = 0.f;
        for (int k = 0; k < FINN; k += 4) {
            float w0 = sh_buf[(k+0)*FOUTN + col];
            float w1 = sh_buf[(k+1)*FOUTN + col];
            float w2 = sh_buf[(k+2)*FOUTN + col];
            float w3 = sh_buf[(k+3)*FOUTN + col];
            #pragma unroll
            for (int i = 0; i < 32; i++) {
                int r = rb + 2*i;
                float4 hv = *(const float4*)&sh_h[r*FINN + k];
                acc[i] += hv.x*w0 + hv.y*w1 + hv.z*w2 + hv.w*w3;
            }
        }
        #pragma unroll
        for (int i = 0; i < 32; i++) sh_sup[(rb + 2*i)*SUP_LD + col] = acc[i];
    }
    __syncthreads();   // done reading W

    // ---- load Wk into buf ----
    {
        const float4* s = (const float4*)g_Wk; float4* d = (float4*)sh_buf;
        for (int i = tid; i < FINN*FOUTN/4; i += 256) d[i] = s[i];
    }
    __syncthreads();

    // ---- Whk = h @ Wk -> sh_whk ----
    {
        float acc[32];
        #pragma unroll
        for (int i = 0; i < 32; i++) acc[i] = 0.f;
        for (int k = 0; k < FINN; k += 4) {
            float w0 = sh_buf[(k+0)*FOUTN + col];
            float w1 = sh_buf[(k+1)*FOUTN + col];
            float w2 = sh_buf[(k+2)*FOUTN + col];
            float w3 = sh_buf[(k+3)*FOUTN + col];
            #pragma unroll
            for (int i = 0; i < 32; i++) {
                int r = rb + 2*i;
                float4 hv = *(const float4*)&sh_h[r*FINN + k];
                acc[i] += hv.x*w0 + hv.y*w1 + hv.z*w2 + hv.w*w3;
            }
        }
        #pragma unroll
        for (int i = 0; i < 32; i++) sh_whk[(rb + 2*i)*SUP_LD + col] = acc[i];
    }
    __syncthreads();   // done reading Wk

    // ---- load Wop_d and Wop_g into buf ----
    {
        const float4* s = (const float4*)g_Wopd; float4* d = (float4*)sh_buf;
        for (int i = tid; i < OPDN*FOUTN/4; i += 256) d[i] = s[i];
        s = (const float4*)g_Wopg; d = (float4*)(sh_buf + OPDN*FOUTN);
        for (int i = tid; i < OPDN*FOUTN/4; i += 256) d[i] = s[i];
    }
    __syncthreads();

    // ---- gates: gd = sigmoid(op@Wop_d + bop_d), gg likewise ----
    float gd[32], gg[32];
    {
        #pragma unroll
        for (int i = 0; i < 32; i++) { gd[i] = 0.f; gg[i] = 0.f; }
        const float* Wg = sh_buf + OPDN*FOUTN;
        for (int k = 0; k < OPDN; k += 4) {
            float d0 = sh_buf[(k+0)*FOUTN + col], d1 = sh_buf[(k+1)*FOUTN + col];
            float d2 = sh_buf[(k+2)*FOUTN + col], d3 = sh_buf[(k+3)*FOUTN + col];
            float e0 = Wg[(k+0)*FOUTN + col],     e1 = Wg[(k+1)*FOUTN + col];
            float e2 = Wg[(k+2)*FOUTN + col],     e3 = Wg[(k+3)*FOUTN + col];
            #pragma unroll
            for (int i = 0; i < 32; i++) {
                int r = rb + 2*i;
                float4 ov = *(const float4*)&sh_op[r*OPDN + k];
                gd[i] += ov.x*d0 + ov.y*d1 + ov.z*d2 + ov.w*d3;
                gg[i] += ov.x*e0 + ov.y*e1 + ov.z*e2 + ov.w*e3;
            }
        }
        float bd = g_bopd[col], bg = g_bopg[col];
        #pragma unroll
        for (int i = 0; i < 32; i++) {
            gd[i] = 1.f / (1.f + __expf(-(gd[i] + bd)));
            gg[i] = 1.f / (1.f + __expf(-(gg[i] + bg)));
        }
    }

    // ---- dense = gd * (adj @ support) + support + b  (into registers) ----
    float dn[32];
    {
        #pragma unroll
        for (int i = 0; i < 32; i++) dn[i] = 0.f;
        for (int j = 0; j < BN; j += 4) {
            float s0 = sh_sup[(j+0)*SUP_LD + col];
            float s1 = sh_sup[(j+1)*SUP_LD + col];
            float s2 = sh_sup[(j+2)*SUP_LD + col];
            float s3 = sh_sup[(j+3)*SUP_LD + col];
            #pragma unroll
            for (int i = 0; i < 32; i++) {
                int r = rb + 2*i;
                float4 av = *(const float4*)&sh_adj[r*BN + j];
                dn[i] += av.x*s0 + av.y*s1 + av.z*s2 + av.w*s3;
            }
        }
        float bv = g_b[col];
        #pragma unroll
        for (int i = 0; i < 32; i++) {
            int r = rb + 2*i;
            dn[i] = gd[i]*dn[i] + sh_sup[r*SUP_LD + col] + bv;
        }
    }
    __syncthreads();   // everyone done reading support & Wop buf

    // ---- write dense over sh_sup; write wa = Whk * a_w into buf ----
    {
        float awv = g_aw[col];
        #pragma unroll
        for (int i = 0; i < 32; i++) {
            int r = rb + 2*i;
            sh_sup[r*SUP_LD + col] = dn[i];
            sh_buf[r*SUP_LD + col] = sh_whk[r*SUP_LD + col] * awv;
        }
    }
    __syncthreads();

    // ---- scores: alpha[i][j] = leaky(dot(wa[i], whk[j])) * adj[i][j] ----
    {
        const int j  = tid & 63;
        const int ib = tid >> 6;           // 0..3
        float sc[16];
        #pragma unroll
        for (int t = 0; t < 16; t++) sc[t] = 0.f;
        for (int m = 0; m < FOUTN; m++) {
            float vj = sh_whk[j*SUP_LD + m];   // bank (j+m)%32: conflict-free
            #pragma unroll
            for (int t = 0; t < 16; t++)
                sc[t] += sh_buf[(ib + 4*t)*SUP_LD + m] * vj;
        }
        #pragma unroll
        for (int t = 0; t < 16; t++) {
            int i = ib + 4*t;
            float s = sc[t];
            s = (s >= 0.f) ? s : SLOPEV * s;
            s *= sh_adj[i*BN + j];
            sh_sc[i*SC_LD + j] = s;
        }
    }
    __syncthreads();

    // ---- softmax over j (row-wise), 4 threads per row ----
    {
        const int row = tid >> 2;
        const int q   = tid & 3;
        float e[16];
        float mx = -1e30f;
        #pragma unroll
        for (int c = 0; c < 16; c++) {
            e[c] = sh_sc[row*SC_LD + q*16 + c];
            mx = fmaxf(mx, e[c]);
        }
        mx = fmaxf(mx, __shfl_xor_sync(0xffffffffu, mx, 1));
        mx = fmaxf(mx, __shfl_xor_sync(0xffffffffu, mx, 2));
        float sum = 0.f;
        #pragma unroll
        for (int c = 0; c < 16; c++) { e[c] = __expf(e[c] - mx); sum += e[c]; }
        sum += __shfl_xor_sync(0xffffffffu, sum, 1);
        sum += __shfl_xor_sync(0xffffffffu, sum, 2);
        float inv = 1.f / sum;
        #pragma unroll
        for (int c = 0; c < 16; c++) sh_sc[row*SC_LD + q*16 + c] = e[c] * inv;
    }
    __syncthreads();

    // ---- hp = gg * (attn @ Whk) ----
    float hp[32];
    {
        #pragma unroll
        for (int i = 0; i < 32; i++) hp[i] = 0.f;
        for (int j = 0; j < BN; j += 4) {
            float w0 = sh_whk[(j+0)*SUP_LD + col];
            float w1 = sh_whk[(j+1)*SUP_LD + col];
            float w2 = sh_whk[(j+2)*SUP_LD + col];
            float w3 = sh_whk[(j+3)*SUP_LD + col];
            #pragma unroll
            for (int i = 0; i < 32; i++) {
                int r = rb + 2*i;
                float4 av = *(const float4*)&sh_sc[r*SC_LD + j];
                hp[i] += av.x*w0 + av.y*w1 + av.z*w2 + av.w*w3;
            }
        }
        #pragma unroll
        for (int i = 0; i < 32; i++) hp[i] *= gg[i];
    }
    __syncthreads();   // done reading whk
    {
        #pragma unroll
        for (int i = 0; i < 32; i++) sh_whk[(rb + 2*i)*SUP_LD + col] = hp[i];
    }
    __syncthreads();

    // ---- LayerNorm stats per row (4 threads/row) ----
    {
        const int row = tid >> 2;
        const int q   = tid & 3;
        float sum = 0.f, sq = 0.f;
        #pragma unroll
        for (int c = 0; c < 32; c++) {
            float v = sh_whk[row*SUP_LD + q*32 + c];
            sum += v; sq += v*v;
        }
        sum += __shfl_xor_sync(0xffffffffu, sum, 1);
        sum += __shfl_xor_sync(0xffffffffu, sum, 2);
        sq  += __shfl_xor_sync(0xffffffffu, sq, 1);
        sq  += __shfl_xor_sync(0xffffffffu, sq, 2);
        float mu  = sum * (1.f / FOUTN);
        float var = sq * (1.f / FOUTN) - mu*mu;
        if (q == 0) { sh_mu[row] = mu; sh_rs[row] = rsqrtf(var + EPSV); }
    }
    __syncthreads();

    // ---- combine & write: out = (dense + LN(hp)*gamma + beta) / 2, coalesced ----
    {
        float gm = g_gamma[col], be = g_beta[col];
        #pragma unroll
        for (int i = 0; i < 32; i++) {
            int r = rb + 2*i;
            float v = (sh_whk[r*SUP_LD + col] - sh_mu[r]) * sh_rs[r] * gm + be;
            outB[r*FOUTN + col] = 0.5f * (sh_sup[r*SUP_LD + col] + v);
        }
    }
}

extern "C" void kernel_launch(void* const* d_in, const int* in_sizes, int n_in,
                              void* d_out, int out_size)
{
    const float* h     = (const float*)d_in[0];
    const float* adj   = (const float*)d_in[1];
    const float* op    = (const float*)d_in[2];
    const float* W     = (const float*)d_in[3];
    const float* b     = (const float*)d_in[4];
    const float* Wopd  = (const float*)d_in[5];
    const float* bopd  = (const float*)d_in[6];
    const float* Wk    = (const float*)d_in[7];
    const float* aw    = (const float*)d_in[8];
    const float* Wopg  = (const float*)d_in[9];
    const float* bopg  = (const float*)d_in[10];
    const float* gamma = (const float*)d_in[11];
    const float* beta  = (const float*)d_in[12];
    float* out = (float*)d_out;

    const int B = in_sizes[0] / (BN * FINN);   // 2048
    const size_t smem_bytes = SMEM_FLOATS * sizeof(float);

    static bool attr_set = false;
    if (!attr_set) {
        cudaFuncSetAttribute(gin_fused_kernel,
                             cudaFuncAttributeMaxDynamicSharedMemorySize,
                             (int)smem_bytes);
        attr_set = true;
    }

    gin_fused_kernel<<<B, 256, smem_bytes>>>(h, adj, op, W, b, Wopd, bopd,
                                             Wk, aw, Wopg, bopg, gamma, beta, out);
}

// round 4
// speedup vs baseline: 1.3984x; 1.3984x over previous
#include <cuda_runtime.h>
#include <math.h>

#define BN    64
#define FINN  96
#define FOUTN 128
#define OPDN  48
#define SUP_LD 132   // padded stride (mult of 4 for float4 rows; %32==4 for conflict-free column reads)
#define SC_LD  68
#define EPSV 1e-5f
#define SLOPEV 0.01f

// shared layout (floats):
//  sh_h    : 64*96   = 6144
//  sh_buf  : 96*128  = 12288   (W -> Wk -> Wop_d|Wop_g -> wa[64*132=8448])
//  sh_adj  : 64*64   = 4096
//  sh_op   : 64*48   = 3072
//  sh_sup  : 64*132  = 8448    (support -> dense, in place)
//  sh_whk  : 64*132  = 8448    (Whk -> hp, in place)
//  sh_sc   : 64*68   = 4352    (alpha -> attn, in place)
//  sh_mu   : 64
//  sh_rs   : 64
#define SMEM_FLOATS (6144 + 12288 + 4096 + 3072 + 8448 + 8448 + 4352 + 64 + 64)

__global__ void __launch_bounds__(512, 1)
gin_fused_kernel(const float* __restrict__ g_h, const float* __restrict__ g_adj,
                 const float* __restrict__ g_op,
                 const float* __restrict__ g_W,  const float* __restrict__ g_b,
                 const float* __restrict__ g_Wopd, const float* __restrict__ g_bopd,
                 const float* __restrict__ g_Wk, const float* __restrict__ g_aw,
                 const float* __restrict__ g_Wopg, const float* __restrict__ g_bopg,
                 const float* __restrict__ g_gamma, const float* __restrict__ g_beta,
                 float* __restrict__ g_out)
{
    extern __shared__ float smem[];
    float* sh_h   = smem;
    float* sh_buf = sh_h + BN * FINN;
    float* sh_adj = sh_buf + FINN * FOUTN;
    float* sh_op  = sh_adj + BN * BN;
    float* sh_sup = sh_op + BN * OPDN;
    float* sh_whk = sh_sup + BN * SUP_LD;
    float* sh_sc  = sh_whk + BN * SUP_LD;
    float* sh_mu  = sh_sc + BN * SC_LD;
    float* sh_rs  = sh_mu + BN;

    const int tid = threadIdx.x;
    const int bb  = blockIdx.x;

    const float* hB   = g_h   + (size_t)bb * BN * FINN;
    const float* adjB = g_adj + (size_t)bb * BN * BN;
    const float* opB  = g_op  + (size_t)bb * BN * OPDN;
    float*       outB = g_out + (size_t)bb * BN * FOUTN;

    // mapping for 64x128 tiles: 4 rows x 4 cols per thread
    const int lane = tid & 31;
    const int wg   = tid >> 5;          // 0..15, uniform per warp
    const int col4 = lane * 4;
    const int r0   = wg * 4;

    // ---- cooperative loads ----
    {
        const float4* s; float4* d; int n4;
        s = (const float4*)hB;   d = (float4*)sh_h;   n4 = BN*FINN/4;
        for (int i = tid; i < n4; i += 512) d[i] = s[i];
        s = (const float4*)g_W;  d = (float4*)sh_buf; n4 = FINN*FOUTN/4;
        for (int i = tid; i < n4; i += 512) d[i] = s[i];
        s = (const float4*)adjB; d = (float4*)sh_adj; n4 = BN*BN/4;
        for (int i = tid; i < n4; i += 512) d[i] = s[i];
        s = (const float4*)opB;  d = (float4*)sh_op;  n4 = BN*OPDN/4;
        for (int i = tid; i < n4; i += 512) d[i] = s[i];
    }
    __syncthreads();

    // ---- support = h @ W -> sh_sup ----
    {
        float4 acc[4];
        #pragma unroll
        for (int i = 0; i < 4; i++) acc[i] = make_float4(0.f,0.f,0.f,0.f);
        for (int k = 0; k < FINN; k += 4) {
            float4 w0 = *(const float4*)&sh_buf[(k+0)*FOUTN + col4];
            float4 w1 = *(const float4*)&sh_buf[(k+1)*FOUTN + col4];
            float4 w2 = *(const float4*)&sh_buf[(k+2)*FOUTN + col4];
            float4 w3 = *(const float4*)&sh_buf[(k+3)*FOUTN + col4];
            #pragma unroll
            for (int ii = 0; ii < 4; ii++) {
                float4 hv = *(const float4*)&sh_h[(r0+ii)*FINN + k];
                acc[ii].x += hv.x*w0.x + hv.y*w1.x + hv.z*w2.x + hv.w*w3.x;
                acc[ii].y += hv.x*w0.y + hv.y*w1.y + hv.z*w2.y + hv.w*w3.y;
                acc[ii].z += hv.x*w0.z + hv.y*w1.z + hv.z*w2.z + hv.w*w3.z;
                acc[ii].w += hv.x*w0.w + hv.y*w1.w + hv.z*w2.w + hv.w*w3.w;
            }
        }
        #pragma unroll
        for (int ii = 0; ii < 4; ii++)
            *(float4*)&sh_sup[(r0+ii)*SUP_LD + col4] = acc[ii];
    }
    __syncthreads();   // done reading W

    // ---- load Wk ----
    {
        const float4* s = (const float4*)g_Wk; float4* d = (float4*)sh_buf;
        for (int i = tid; i < FINN*FOUTN/4; i += 512) d[i] = s[i];
    }
    __syncthreads();

    // ---- Whk = h @ Wk -> sh_whk ----
    {
        float4 acc[4];
        #pragma unroll
        for (int i = 0; i < 4; i++) acc[i] = make_float4(0.f,0.f,0.f,0.f);
        for (int k = 0; k < FINN; k += 4) {
            float4 w0 = *(const float4*)&sh_buf[(k+0)*FOUTN + col4];
            float4 w1 = *(const float4*)&sh_buf[(k+1)*FOUTN + col4];
            float4 w2 = *(const float4*)&sh_buf[(k+2)*FOUTN + col4];
            float4 w3 = *(const float4*)&sh_buf[(k+3)*FOUTN + col4];
            #pragma unroll
            for (int ii = 0; ii < 4; ii++) {
                float4 hv = *(const float4*)&sh_h[(r0+ii)*FINN + k];
                acc[ii].x += hv.x*w0.x + hv.y*w1.x + hv.z*w2.x + hv.w*w3.x;
                acc[ii].y += hv.x*w0.y + hv.y*w1.y + hv.z*w2.y + hv.w*w3.y;
                acc[ii].z += hv.x*w0.z + hv.y*w1.z + hv.z*w2.z + hv.w*w3.z;
                acc[ii].w += hv.x*w0.w + hv.y*w1.w + hv.z*w2.w + hv.w*w3.w;
            }
        }
        #pragma unroll
        for (int ii = 0; ii < 4; ii++)
            *(float4*)&sh_whk[(r0+ii)*SUP_LD + col4] = acc[ii];
    }
    __syncthreads();   // done reading Wk

    // ---- load Wop_d | Wop_g (exactly fills sh_buf: 2*48*128 = 12288) ----
    {
        const float4* s = (const float4*)g_Wopd; float4* d = (float4*)sh_buf;
        for (int i = tid; i < OPDN*FOUTN/4; i += 512) d[i] = s[i];
        s = (const float4*)g_Wopg; d = (float4*)(sh_buf + OPDN*FOUTN);
        for (int i = tid; i < OPDN*FOUTN/4; i += 512) d[i] = s[i];
    }
    __syncthreads();

    // ---- gates ----
    float4 gd[4], gg[4];
    {
        #pragma unroll
        for (int i = 0; i < 4; i++) { gd[i] = make_float4(0.f,0.f,0.f,0.f); gg[i] = gd[i]; }
        const float* Wg = sh_buf + OPDN*FOUTN;
        for (int k = 0; k < OPDN; k += 4) {
            float4 d0 = *(const float4*)&sh_buf[(k+0)*FOUTN + col4];
            float4 d1 = *(const float4*)&sh_buf[(k+1)*FOUTN + col4];
            float4 d2 = *(const float4*)&sh_buf[(k+2)*FOUTN + col4];
            float4 d3 = *(const float4*)&sh_buf[(k+3)*FOUTN + col4];
            float4 e0 = *(const float4*)&Wg[(k+0)*FOUTN + col4];
            float4 e1 = *(const float4*)&Wg[(k+1)*FOUTN + col4];
            float4 e2 = *(const float4*)&Wg[(k+2)*FOUTN + col4];
            float4 e3 = *(const float4*)&Wg[(k+3)*FOUTN + col4];
            #pragma unroll
            for (int ii = 0; ii < 4; ii++) {
                float4 ov = *(const float4*)&sh_op[(r0+ii)*OPDN + k];
                gd[ii].x += ov.x*d0.x + ov.y*d1.x + ov.z*d2.x + ov.w*d3.x;
                gd[ii].y += ov.x*d0.y + ov.y*d1.y + ov.z*d2.y + ov.w*d3.y;
                gd[ii].z += ov.x*d0.z + ov.y*d1.z + ov.z*d2.z + ov.w*d3.z;
                gd[ii].w += ov.x*d0.w + ov.y*d1.w + ov.z*d2.w + ov.w*d3.w;
                gg[ii].x += ov.x*e0.x + ov.y*e1.x + ov.z*e2.x + ov.w*e3.x;
                gg[ii].y += ov.x*e0.y + ov.y*e1.y + ov.z*e2.y + ov.w*e3.y;
                gg[ii].z += ov.x*e0.z + ov.y*e1.z + ov.z*e2.z + ov.w*e3.z;
                gg[ii].w += ov.x*e0.w + ov.y*e1.w + ov.z*e2.w + ov.w*e3.w;
            }
        }
        float4 bd = *(const float4*)&g_bopd[col4];
        float4 bg = *(const float4*)&g_bopg[col4];
        #pragma unroll
        for (int ii = 0; ii < 4; ii++) {
            gd[ii].x = 1.f/(1.f+__expf(-(gd[ii].x+bd.x)));
            gd[ii].y = 1.f/(1.f+__expf(-(gd[ii].y+bd.y)));
            gd[ii].z = 1.f/(1.f+__expf(-(gd[ii].z+bd.z)));
            gd[ii].w = 1.f/(1.f+__expf(-(gd[ii].w+bd.w)));
            gg[ii].x = 1.f/(1.f+__expf(-(gg[ii].x+bg.x)));
            gg[ii].y = 1.f/(1.f+__expf(-(gg[ii].y+bg.y)));
            gg[ii].z = 1.f/(1.f+__expf(-(gg[ii].z+bg.z)));
            gg[ii].w = 1.f/(1.f+__expf(-(gg[ii].w+bg.w)));
        }
    }

    // ---- dense = gd * (adj @ support) + support + b ----
    float4 dn[4];
    {
        #pragma unroll
        for (int i = 0; i < 4; i++) dn[i] = make_float4(0.f,0.f,0.f,0.f);
        for (int j = 0; j < BN; j += 4) {
            float4 s0 = *(const float4*)&sh_sup[(j+0)*SUP_LD + col4];
            float4 s1 = *(const float4*)&sh_sup[(j+1)*SUP_LD + col4];
            float4 s2 = *(const float4*)&sh_sup[(j+2)*SUP_LD + col4];
            float4 s3 = *(const float4*)&sh_sup[(j+3)*SUP_LD + col4];
            #pragma unroll
            for (int ii = 0; ii < 4; ii++) {
                float4 av = *(const float4*)&sh_adj[(r0+ii)*BN + j];
                dn[ii].x += av.x*s0.x + av.y*s1.x + av.z*s2.x + av.w*s3.x;
                dn[ii].y += av.x*s0.y + av.y*s1.y + av.z*s2.y + av.w*s3.y;
                dn[ii].z += av.x*s0.z + av.y*s1.z + av.z*s2.z + av.w*s3.z;
                dn[ii].w += av.x*s0.w + av.y*s1.w + av.z*s2.w + av.w*s3.w;
            }
        }
        float4 bv = *(const float4*)&g_b[col4];
        #pragma unroll
        for (int ii = 0; ii < 4; ii++) {
            float4 sp = *(const float4*)&sh_sup[(r0+ii)*SUP_LD + col4];
            dn[ii].x = gd[ii].x*dn[ii].x + sp.x + bv.x;
            dn[ii].y = gd[ii].y*dn[ii].y + sp.y + bv.y;
            dn[ii].z = gd[ii].z*dn[ii].z + sp.z + bv.z;
            dn[ii].w = gd[ii].w*dn[ii].w + sp.w + bv.w;
        }
    }
    __syncthreads();   // everyone done reading support & Wop buf

    // ---- write dense over sh_sup; wa = Whk * a_w into sh_buf ----
    {
        float4 awv = *(const float4*)&g_aw[col4];
        #pragma unroll
        for (int ii = 0; ii < 4; ii++) {
            *(float4*)&sh_sup[(r0+ii)*SUP_LD + col4] = dn[ii];
            float4 wv = *(const float4*)&sh_whk[(r0+ii)*SUP_LD + col4];
            wv.x *= awv.x; wv.y *= awv.y; wv.z *= awv.z; wv.w *= awv.w;
            *(float4*)&sh_buf[(r0+ii)*SUP_LD + col4] = wv;
        }
    }
    __syncthreads();

    // ---- scores: alpha[i][j] = leaky(dot(wa[i], whk[j])) * adj[i][j] ----
    // thread handles i in {wg*4..+3}, j in {lane, lane+32}
    {
        float sc[4][2];
        #pragma unroll
        for (int ii = 0; ii < 4; ii++) { sc[ii][0] = 0.f; sc[ii][1] = 0.f; }
        const int j0 = lane, j1 = lane + 32;
        for (int m = 0; m < FOUTN; m += 4) {
            float4 v0 = *(const float4*)&sh_whk[j0*SUP_LD + m];  // stride 132 -> 4 banks/lane: conflict-free
            float4 v1 = *(const float4*)&sh_whk[j1*SUP_LD + m];
            #pragma unroll
            for (int ii = 0; ii < 4; ii++) {
                float4 av = *(const float4*)&sh_buf[(r0+ii)*SUP_LD + m];  // broadcast
                sc[ii][0] += av.x*v0.x + av.y*v0.y + av.z*v0.z + av.w*v0.w;
                sc[ii][1] += av.x*v1.x + av.y*v1.y + av.z*v1.z + av.w*v1.w;
            }
        }
        #pragma unroll
        for (int ii = 0; ii < 4; ii++) {
            int i = r0 + ii;
            float s0 = sc[ii][0]; s0 = (s0 >= 0.f) ? s0 : SLOPEV*s0;
            float s1 = sc[ii][1]; s1 = (s1 >= 0.f) ? s1 : SLOPEV*s1;
            sh_sc[i*SC_LD + j0] = s0 * sh_adj[i*BN + j0];
            sh_sc[i*SC_LD + j1] = s1 * sh_adj[i*BN + j1];
        }
    }
    __syncthreads();

    // ---- softmax over j, 8 threads/row ----
    {
        const int row = tid >> 3;
        const int q   = tid & 7;
        float4 e0 = *(const float4*)&sh_sc[row*SC_LD + q*8];
        float4 e1 = *(const float4*)&sh_sc[row*SC_LD + q*8 + 4];
        float mx = fmaxf(fmaxf(fmaxf(e0.x,e0.y),fmaxf(e0.z,e0.w)),
                         fmaxf(fmaxf(e1.x,e1.y),fmaxf(e1.z,e1.w)));
        mx = fmaxf(mx, __shfl_xor_sync(0xffffffffu, mx, 1));
        mx = fmaxf(mx, __shfl_xor_sync(0xffffffffu, mx, 2));
        mx = fmaxf(mx, __shfl_xor_sync(0xffffffffu, mx, 4));
        e0.x = __expf(e0.x - mx); e0.y = __expf(e0.y - mx);
        e0.z = __expf(e0.z - mx); e0.w = __expf(e0.w - mx);
        e1.x = __expf(e1.x - mx); e1.y = __expf(e1.y - mx);
        e1.z = __expf(e1.z - mx); e1.w = __expf(e1.w - mx);
        float sum = e0.x+e0.y+e0.z+e0.w+e1.x+e1.y+e1.z+e1.w;
        sum += __shfl_xor_sync(0xffffffffu, sum, 1);
        sum += __shfl_xor_sync(0xffffffffu, sum, 2);
        sum += __shfl_xor_sync(0xffffffffu, sum, 4);
        float inv = 1.f / sum;
        e0.x*=inv; e0.y*=inv; e0.z*=inv; e0.w*=inv;
        e1.x*=inv; e1.y*=inv; e1.z*=inv; e1.w*=inv;
        *(float4*)&sh_sc[row*SC_LD + q*8]     = e0;
        *(float4*)&sh_sc[row*SC_LD + q*8 + 4] = e1;
    }
    __syncthreads();

    // ---- hp = gg * (attn @ Whk) ----
    float4 hp[4];
    {
        #pragma unroll
        for (int i = 0; i < 4; i++) hp[i] = make_float4(0.f,0.f,0.f,0.f);
        for (int j = 0; j < BN; j += 4) {
            float4 w0 = *(const float4*)&sh_whk[(j+0)*SUP_LD + col4];
            float4 w1 = *(const float4*)&sh_whk[(j+1)*SUP_LD + col4];
            float4 w2 = *(const float4*)&sh_whk[(j+2)*SUP_LD + col4];
            float4 w3 = *(const float4*)&sh_whk[(j+3)*SUP_LD + col4];
            #pragma unroll
            for (int ii = 0; ii < 4; ii++) {
                float4 av = *(const float4*)&sh_sc[(r0+ii)*SC_LD + j];
                hp[ii].x += av.x*w0.x + av.y*w1.x + av.z*w2.x + av.w*w3.x;
                hp[ii].y += av.x*w0.y + av.y*w1.y + av.z*w2.y + av.w*w3.y;
                hp[ii].z += av.x*w0.z + av.y*w1.z + av.z*w2.z + av.w*w3.z;
                hp[ii].w += av.x*w0.w + av.y*w1.w + av.z*w2.w + av.w*w3.w;
            }
        }
        #pragma unroll
        for (int ii = 0; ii < 4; ii++) {
            hp[ii].x *= gg[ii].x; hp[ii].y *= gg[ii].y;
            hp[ii].z *= gg[ii].z; hp[ii].w *= gg[ii].w;
        }
    }
    __syncthreads();   // done reading whk
    {
        #pragma unroll
        for (int ii = 0; ii < 4; ii++)
            *(float4*)&sh_whk[(r0+ii)*SUP_LD + col4] = hp[ii];
    }
    __syncthreads();

    // ---- LayerNorm stats (8 threads/row, 16 values each) ----
    {
        const int row = tid >> 3;
        const int q   = tid & 7;
        float sum = 0.f, sq = 0.f;
        #pragma unroll
        for (int c = 0; c < 4; c++) {
            float4 v = *(const float4*)&sh_whk[row*SUP_LD + q*16 + c*4];
            sum += v.x+v.y+v.z+v.w;
            sq  += v.x*v.x + v.y*v.y + v.z*v.z + v.w*v.w;
        }
        sum += __shfl_xor_sync(0xffffffffu, sum, 1);
        sum += __shfl_xor_sync(0xffffffffu, sum, 2);
        sum += __shfl_xor_sync(0xffffffffu, sum, 4);
        sq  += __shfl_xor_sync(0xffffffffu, sq, 1);
        sq  += __shfl_xor_sync(0xffffffffu, sq, 2);
        sq  += __shfl_xor_sync(0xffffffffu, sq, 4);
        float mu  = sum * (1.f / FOUTN);
        float var = sq * (1.f / FOUTN) - mu*mu;
        if (q == 0) { sh_mu[row] = mu; sh_rs[row] = rsqrtf(var + EPSV); }
    }
    __syncthreads();

    // ---- combine & write ----
    {
        float4 gm = *(const float4*)&g_gamma[col4];
        float4 be = *(const float4*)&g_beta[col4];
        #pragma unroll
        for (int ii = 0; ii < 4; ii++) {
            int r = r0 + ii;
            float mu = sh_mu[r], rs = sh_rs[r];
            float4 v  = *(const float4*)&sh_whk[r*SUP_LD + col4];
            float4 dd = *(const float4*)&sh_sup[r*SUP_LD + col4];
            float4 o;
            o.x = 0.5f*(dd.x + (v.x - mu)*rs*gm.x + be.x);
            o.y = 0.5f*(dd.y + (v.y - mu)*rs*gm.y + be.y);
            o.z = 0.5f*(dd.z + (v.z - mu)*rs*gm.z + be.z);
            o.w = 0.5f*(dd.w + (v.w - mu)*rs*gm.w + be.w);
            *(float4*)&outB[r*FOUTN + col4] = o;
        }
    }
}

extern "C" void kernel_launch(void* const* d_in, const int* in_sizes, int n_in,
                              void* d_out, int out_size)
{
    const float* h     = (const float*)d_in[0];
    const float* adj   = (const float*)d_in[1];
    const float* op    = (const float*)d_in[2];
    const float* W     = (const float*)d_in[3];
    const float* b     = (const float*)d_in[4];
    const float* Wopd  = (const float*)d_in[5];
    const float* bopd  = (const float*)d_in[6];
    const float* Wk    = (const float*)d_in[7];
    const float* aw    = (const float*)d_in[8];
    const float* Wopg  = (const float*)d_in[9];
    const float* bopg  = (const float*)d_in[10];
    const float* gamma = (const float*)d_in[11];
    const float* beta  = (const float*)d_in[12];
    float* out = (float*)d_out;

    const int B = in_sizes[0] / (BN * FINN);   // 2048
    const size_t smem_bytes = SMEM_FLOATS * sizeof(float);

    static bool attr_set = false;
    if (!attr_set) {
        cudaFuncSetAttribute(gin_fused_kernel,
                             cudaFuncAttributeMaxDynamicSharedMemorySize,
                             (int)smem_bytes);
        attr_set = true;
    }

    gin_fused_kernel<<<B, 512, smem_bytes>>>(h, adj, op, W, b, Wopd, bopd,
                                             Wk, aw, Wopg, bopg, gamma, beta, out);
}

// round 7
// speedup vs baseline: 2.8120x; 2.0108x over previous
#include <cuda_runtime.h>
#include <stdint.h>
#include <math.h>

#define BN    64
#define FINN  96
#define FOUTN 128
#define OPDN  48

#define LDH   100   // A-operand pads: LD%32==4 -> conflict-free A-fragment loads
#define LDADJ 68
#define LDSC  68
#define LDOP  52
#define LDW   136   // B-operand pads: LD%32==8 -> conflict-free B-fragment loads
#define EPSV 1e-5f
#define SLOPEV 0.01f

// shared layout (floats)
#define OFF_H    0
#define OFF_BUF  (OFF_H   + BN*LDH)        // 6400   (96x136 weights buffer)
#define OFF_ADJ  (OFF_BUF + 96*LDW)        // 19456
#define OFF_OP   (OFF_ADJ + BN*LDADJ)      // 23808
#define OFF_SUP  (OFF_OP  + BN*LDOP)       // 27136
#define OFF_WHK  (OFF_SUP + BN*LDW)        // 35840
#define OFF_SC   (OFF_WHK + BN*LDW)        // 44544
#define OFF_AW   (OFF_SC  + BN*LDSC)       // 48896
#define OFF_B    (OFF_AW  + 128)
#define OFF_BD   (OFF_B   + 128)
#define OFF_BG   (OFF_BD  + 128)
#define OFF_MU   (OFF_BG  + 128)
#define OFF_RS   (OFF_MU  + 64)
#define SMEM_FLOATS (OFF_RS + 64)          // 49536 floats = 198144 B

__device__ __forceinline__ uint32_t f2tf(float f) {
    uint32_t u;
    asm("cvt.rna.tf32.f32 %0, %1;" : "=r"(u) : "f"(f));
    return u;
}

__device__ __forceinline__ void mma_tf32(float c[4],
                                         uint32_t a0, uint32_t a1, uint32_t a2, uint32_t a3,
                                         uint32_t b0, uint32_t b1) {
    asm volatile(
        "mma.sync.aligned.m16n8k8.row.col.f32.tf32.tf32.f32 "
        "{%0,%1,%2,%3}, {%4,%5,%6,%7}, {%8,%9}, {%0,%1,%2,%3};"
        : "+f"(c[0]), "+f"(c[1]), "+f"(c[2]), "+f"(c[3])
        : "r"(a0), "r"(a1), "r"(a2), "r"(a3), "r"(b0), "r"(b1));
}

// D[m0..m0+16, n0..n0+8*NB] += A[m0.., k] * B[k, n0..], K = 8*KSTEPS
// B stored [k][n] row-major in SMEM.
template<int KSTEPS, int NB>
__device__ __forceinline__ void gemm_frag(const float* __restrict__ A, int lda,
                                          const float* __restrict__ B, int ldb,
                                          int m0, int n0, int lr, int lc,
                                          float acc[NB][4]) {
    #pragma unroll
    for (int ks = 0; ks < KSTEPS; ks++) {
        const int k0 = ks * 8;
        uint32_t a0 = f2tf(A[(m0+lr  )*lda + k0+lc  ]);
        uint32_t a1 = f2tf(A[(m0+lr+8)*lda + k0+lc  ]);
        uint32_t a2 = f2tf(A[(m0+lr  )*lda + k0+lc+4]);
        uint32_t a3 = f2tf(A[(m0+lr+8)*lda + k0+lc+4]);
        #pragma unroll
        for (int nb = 0; nb < NB; nb++) {
            uint32_t b0 = f2tf(B[(k0+lc  )*ldb + n0+nb*8+lr]);
            uint32_t b1 = f2tf(B[(k0+lc+4)*ldb + n0+nb*8+lr]);
            mma_tf32(acc[nb], a0, a1, a2, a3, b0, b1);
        }
    }
}

__device__ __forceinline__ void store_frag4(float* D, int ldd, int m0, int n0,
                                            int lr, int lc, float acc[4][4]) {
    #pragma unroll
    for (int nb = 0; nb < 4; nb++) {
        int c0 = n0 + nb*8 + 2*lc;
        D[(m0+lr  )*ldd + c0  ] = acc[nb][0];
        D[(m0+lr  )*ldd + c0+1] = acc[nb][1];
        D[(m0+lr+8)*ldd + c0  ] = acc[nb][2];
        D[(m0+lr+8)*ldd + c0+1] = acc[nb][3];
    }
}

__global__ void __launch_bounds__(512, 1)
gin_mma_kernel(const float* __restrict__ g_h, const float* __restrict__ g_adj,
               const float* __restrict__ g_op,
               const float* __restrict__ g_W,  const float* __restrict__ g_b,
               const float* __restrict__ g_Wopd, const float* __restrict__ g_bopd,
               const float* __restrict__ g_Wk, const float* __restrict__ g_aw,
               const float* __restrict__ g_Wopg, const float* __restrict__ g_bopg,
               const float* __restrict__ g_gamma, const float* __restrict__ g_beta,
               float* __restrict__ g_out)
{
    extern __shared__ float smem[];
    float* sh_h   = smem + OFF_H;
    float* sh_buf = smem + OFF_BUF;
    float* sh_adj = smem + OFF_ADJ;
    float* sh_op  = smem + OFF_OP;
    float* sh_sup = smem + OFF_SUP;
    float* sh_whk = smem + OFF_WHK;
    float* sh_sc  = smem + OFF_SC;
    float* sh_aw  = smem + OFF_AW;
    float* sh_b   = smem + OFF_B;
    float* sh_bd  = smem + OFF_BD;
    float* sh_bg  = smem + OFF_BG;
    float* sh_mu  = smem + OFF_MU;
    float* sh_rs  = smem + OFF_RS;

    const int tid  = threadIdx.x;
    const int lane = tid & 31;
    const int w    = tid >> 5;          // 0..15
    const int lr   = lane >> 2;         // 0..7
    const int lc   = lane & 3;          // 0..3
    const int m0   = (w & 3) * 16;      // row block
    const int n0   = (w >> 2) * 32;     // col block (128-col GEMMs)
    const int j0   = (w >> 2) * 16;     // col block (64-col scores)
    const int bb   = blockIdx.x;

    const float* hB   = g_h   + (size_t)bb * BN * FINN;
    const float* adjB = g_adj + (size_t)bb * BN * BN;
    const float* opB  = g_op  + (size_t)bb * BN * OPDN;
    float*       outB = g_out + (size_t)bb * BN * FOUTN;

    // ---- cooperative loads with padded strides ----
    {
        for (int i = tid; i < BN*24; i += 512) {           // h 64x96
            int r = i / 24, c = i % 24;
            ((float4*)(sh_h + r*LDH))[c] = ((const float4*)hB)[i];
        }
        for (int i = tid; i < 96*32; i += 512) {           // W 96x128
            int r = i / 32, c = i % 32;
            ((float4*)(sh_buf + r*LDW))[c] = ((const float4*)g_W)[i];
        }
        for (int i = tid; i < BN*16; i += 512) {           // adj 64x64
            int r = i / 16, c = i % 16;
            ((float4*)(sh_adj + r*LDADJ))[c] = ((const float4*)adjB)[i];
        }
        for (int i = tid; i < BN*12; i += 512) {           // op 64x48
            int r = i / 12, c = i % 12;
            ((float4*)(sh_op + r*LDOP))[c] = ((const float4*)opB)[i];
        }
        if (tid < 128) {
            sh_aw[tid] = g_aw[tid];
            sh_b[tid]  = g_b[tid];
            sh_bd[tid] = g_bopd[tid];
            sh_bg[tid] = g_bopg[tid];
        }
    }
    __syncthreads();

    // ---- support = h @ W ----
    {
        float acc[4][4];
        #pragma unroll
        for (int a = 0; a < 4; a++)
            #pragma unroll
            for (int t = 0; t < 4; t++) acc[a][t] = 0.f;
        gemm_frag<12,4>(sh_h, LDH, sh_buf, LDW, m0, n0, lr, lc, acc);
        store_frag4(sh_sup, LDW, m0, n0, lr, lc, acc);
    }
    __syncthreads();   // done reading W

    // ---- load Wk ----
    for (int i = tid; i < 96*32; i += 512) {
        int r = i / 32, c = i % 32;
        ((float4*)(sh_buf + r*LDW))[c] = ((const float4*)g_Wk)[i];
    }
    __syncthreads();

    // ---- Whk = h @ Wk ----
    {
        float acc[4][4];
        #pragma unroll
        for (int a = 0; a < 4; a++)
            #pragma unroll
            for (int t = 0; t < 4; t++) acc[a][t] = 0.f;
        gemm_frag<12,4>(sh_h, LDH, sh_buf, LDW, m0, n0, lr, lc, acc);
        store_frag4(sh_whk, LDW, m0, n0, lr, lc, acc);
    }
    __syncthreads();   // done reading Wk

    // ---- load Wop_d (rows 0..47) and Wop_g (at +48*LDW) ----
    for (int i = tid; i < 48*32; i += 512) {
        int r = i / 32, c = i % 32;
        ((float4*)(sh_buf + r*LDW))[c]            = ((const float4*)g_Wopd)[i];
        ((float4*)(sh_buf + (48+r)*LDW))[c]       = ((const float4*)g_Wopg)[i];
    }
    __syncthreads();

    // ---- gates: gd = sigmoid(op@Wop_d + bd), gg = sigmoid(op@Wop_g + bg) ----
    float gdv[4][4], ggv[4][4];
    {
        #pragma unroll
        for (int a = 0; a < 4; a++)
            #pragma unroll
            for (int t = 0; t < 4; t++) { gdv[a][t] = 0.f; ggv[a][t] = 0.f; }
        const float* Wg = sh_buf + 48*LDW;
        #pragma unroll
        for (int ks = 0; ks < 6; ks++) {
            const int k0 = ks * 8;
            uint32_t a0 = f2tf(sh_op[(m0+lr  )*LDOP + k0+lc  ]);
            uint32_t a1 = f2tf(sh_op[(m0+lr+8)*LDOP + k0+lc  ]);
            uint32_t a2 = f2tf(sh_op[(m0+lr  )*LDOP + k0+lc+4]);
            uint32_t a3 = f2tf(sh_op[(m0+lr+8)*LDOP + k0+lc+4]);
            #pragma unroll
            for (int nb = 0; nb < 4; nb++) {
                uint32_t d0 = f2tf(sh_buf[(k0+lc  )*LDW + n0+nb*8+lr]);
                uint32_t d1 = f2tf(sh_buf[(k0+lc+4)*LDW + n0+nb*8+lr]);
                mma_tf32(gdv[nb], a0, a1, a2, a3, d0, d1);
                uint32_t e0 = f2tf(Wg[(k0+lc  )*LDW + n0+nb*8+lr]);
                uint32_t e1 = f2tf(Wg[(k0+lc+4)*LDW + n0+nb*8+lr]);
                mma_tf32(ggv[nb], a0, a1, a2, a3, e0, e1);
            }
        }
        #pragma unroll
        for (int nb = 0; nb < 4; nb++) {
            int cA = n0 + nb*8 + 2*lc, cB = cA + 1;
            gdv[nb][0] = 1.f/(1.f+__expf(-(gdv[nb][0] + sh_bd[cA])));
            gdv[nb][1] = 1.f/(1.f+__expf(-(gdv[nb][1] + sh_bd[cB])));
            gdv[nb][2] = 1.f/(1.f+__expf(-(gdv[nb][2] + sh_bd[cA])));
            gdv[nb][3] = 1.f/(1.f+__expf(-(gdv[nb][3] + sh_bd[cB])));
            ggv[nb][0] = 1.f/(1.f+__expf(-(ggv[nb][0] + sh_bg[cA])));
            ggv[nb][1] = 1.f/(1.f+__expf(-(ggv[nb][1] + sh_bg[cB])));
            ggv[nb][2] = 1.f/(1.f+__expf(-(ggv[nb][2] + sh_bg[cA])));
            ggv[nb][3] = 1.f/(1.f+__expf(-(ggv[nb][3] + sh_bg[cB])));
        }
    }

    // ---- dense = gd * (adj @ support) + support + b ----
    float dnv[4][4];
    {
        #pragma unroll
        for (int a = 0; a < 4; a++)
            #pragma unroll
            for (int t = 0; t < 4; t++) dnv[a][t] = 0.f;
        gemm_frag<8,4>(sh_adj, LDADJ, sh_sup, LDW, m0, n0, lr, lc, dnv);
        #pragma unroll
        for (int nb = 0; nb < 4; nb++) {
            int cA = n0 + nb*8 + 2*lc, cB = cA + 1;
            int rA = m0 + lr, rB = m0 + lr + 8;
            dnv[nb][0] = gdv[nb][0]*dnv[nb][0] + sh_sup[rA*LDW + cA] + sh_b[cA];
            dnv[nb][1] = gdv[nb][1]*dnv[nb][1] + sh_sup[rA*LDW + cB] + sh_b[cB];
            dnv[nb][2] = gdv[nb][2]*dnv[nb][2] + sh_sup[rB*LDW + cA] + sh_b[cA];
            dnv[nb][3] = gdv[nb][3]*dnv[nb][3] + sh_sup[rB*LDW + cB] + sh_b[cB];
        }
    }
    __syncthreads();   // everyone done reading sh_sup
    store_frag4(sh_sup, LDW, m0, n0, lr, lc, dnv);   // dense -> sh_sup

    // ---- scores[i][j] = leaky(sum_m whk[i][m]*aw[m]*whk[j][m]) * adj[i][j] ----
    // B[k=m][n=j] = whk[j][m]: whk is stored [j][m], so index rows by j, cols by m.
    {
        float sc[2][4];
        #pragma unroll
        for (int a = 0; a < 2; a++)
            #pragma unroll
            for (int t = 0; t < 4; t++) sc[a][t] = 0.f;
        #pragma unroll
        for (int ks = 0; ks < 16; ks++) {
            const int k0 = ks * 8;
            float aw0 = sh_aw[k0+lc], aw1 = sh_aw[k0+lc+4];
            uint32_t a0 = f2tf(sh_whk[(m0+lr  )*LDW + k0+lc  ] * aw0);
            uint32_t a1 = f2tf(sh_whk[(m0+lr+8)*LDW + k0+lc  ] * aw0);
            uint32_t a2 = f2tf(sh_whk[(m0+lr  )*LDW + k0+lc+4] * aw1);
            uint32_t a3 = f2tf(sh_whk[(m0+lr+8)*LDW + k0+lc+4] * aw1);
            #pragma unroll
            for (int nb = 0; nb < 2; nb++) {
                int jrow = j0 + nb*8 + lr;
                uint32_t b0 = f2tf(sh_whk[jrow*LDW + k0+lc  ]);
                uint32_t b1 = f2tf(sh_whk[jrow*LDW + k0+lc+4]);
                mma_tf32(sc[nb], a0, a1, a2, a3, b0, b1);
            }
        }
        #pragma unroll
        for (int nb = 0; nb < 2; nb++) {
            int jA = j0 + nb*8 + 2*lc, jB = jA + 1;
            int iA = m0 + lr, iB = m0 + lr + 8;
            float s;
            s = sc[nb][0]; s = (s >= 0.f) ? s : SLOPEV*s; sh_sc[iA*LDSC + jA] = s * sh_adj[iA*LDADJ + jA];
            s = sc[nb][1]; s = (s >= 0.f) ? s : SLOPEV*s; sh_sc[iA*LDSC + jB] = s * sh_adj[iA*LDADJ + jB];
            s = sc[nb][2]; s = (s >= 0.f) ? s : SLOPEV*s; sh_sc[iB*LDSC + jA] = s * sh_adj[iB*LDADJ + jA];
            s = sc[nb][3]; s = (s >= 0.f) ? s : SLOPEV*s; sh_sc[iB*LDSC + jB] = s * sh_adj[iB*LDADJ + jB];
        }
    }
    __syncthreads();

    // ---- softmax over j, 8 threads/row ----
    {
        const int row = tid >> 3;
        const int q   = tid & 7;
        float4 e0 = *(const float4*)&sh_sc[row*LDSC + q*8];
        float4 e1 = *(const float4*)&sh_sc[row*LDSC + q*8 + 4];
        float mx = fmaxf(fmaxf(fmaxf(e0.x,e0.y),fmaxf(e0.z,e0.w)),
                         fmaxf(fmaxf(e1.x,e1.y),fmaxf(e1.z,e1.w)));
        mx = fmaxf(mx, __shfl_xor_sync(0xffffffffu, mx, 1));
        mx = fmaxf(mx, __shfl_xor_sync(0xffffffffu, mx, 2));
        mx = fmaxf(mx, __shfl_xor_sync(0xffffffffu, mx, 4));
        e0.x = __expf(e0.x - mx); e0.y = __expf(e0.y - mx);
        e0.z = __expf(e0.z - mx); e0.w = __expf(e0.w - mx);
        e1.x = __expf(e1.x - mx); e1.y = __expf(e1.y - mx);
        e1.z = __expf(e1.z - mx); e1.w = __expf(e1.w - mx);
        float sum = e0.x+e0.y+e0.z+e0.w+e1.x+e1.y+e1.z+e1.w;
        sum += __shfl_xor_sync(0xffffffffu, sum, 1);
        sum += __shfl_xor_sync(0xffffffffu, sum, 2);
        sum += __shfl_xor_sync(0xffffffffu, sum, 4);
        float inv = 1.f / sum;
        e0.x*=inv; e0.y*=inv; e0.z*=inv; e0.w*=inv;
        e1.x*=inv; e1.y*=inv; e1.z*=inv; e1.w*=inv;
        *(float4*)&sh_sc[row*LDSC + q*8]     = e0;
        *(float4*)&sh_sc[row*LDSC + q*8 + 4] = e1;
    }
    __syncthreads();

    // ---- hp = gg * (attn @ Whk) ----
    {
        float hpv[4][4];
        #pragma unroll
        for (int a = 0; a < 4; a++)
            #pragma unroll
            for (int t = 0; t < 4; t++) hpv[a][t] = 0.f;
        gemm_frag<8,4>(sh_sc, LDSC, sh_whk, LDW, m0, n0, lr, lc, hpv);
        #pragma unroll
        for (int nb = 0; nb < 4; nb++)
            #pragma unroll
            for (int t = 0; t < 4; t++) hpv[nb][t] *= ggv[nb][t];
        __syncthreads();   // everyone done reading sh_whk
        store_frag4(sh_whk, LDW, m0, n0, lr, lc, hpv);
    }
    __syncthreads();

    // ---- LayerNorm stats (8 threads/row) ----
    {
        const int row = tid >> 3;
        const int q   = tid & 7;
        float sum = 0.f, sq = 0.f;
        #pragma unroll
        for (int c = 0; c < 4; c++) {
            float4 v = *(const float4*)&sh_whk[row*LDW + q*16 + c*4];
            sum += v.x+v.y+v.z+v.w;
            sq  += v.x*v.x + v.y*v.y + v.z*v.z + v.w*v.w;
        }
        sum += __shfl_xor_sync(0xffffffffu, sum, 1);
        sum += __shfl_xor_sync(0xffffffffu, sum, 2);
        sum += __shfl_xor_sync(0xffffffffu, sum, 4);
        sq  += __shfl_xor_sync(0xffffffffu, sq, 1);
        sq  += __shfl_xor_sync(0xffffffffu, sq, 2);
        sq  += __shfl_xor_sync(0xffffffffu, sq, 4);
        float mu  = sum * (1.f / FOUTN);
        float var = sq * (1.f / FOUTN) - mu*mu;
        if (q == 0) { sh_mu[row] = mu; sh_rs[row] = rsqrtf(var + EPSV); }
    }
    __syncthreads();

    // ---- combine & write ----
    {
        const int col4 = lane * 4;
        const int r0v  = w * 4;
        float4 gm = *(const float4*)&g_gamma[col4];
        float4 be = *(const float4*)&g_beta[col4];
        #pragma unroll
        for (int ii = 0; ii < 4; ii++) {
            int r = r0v + ii;
            float mu = sh_mu[r], rs = sh_rs[r];
            float4 v  = *(const float4*)&sh_whk[r*LDW + col4];
            float4 dd = *(const float4*)&sh_sup[r*LDW + col4];
            float4 o;
            o.x = 0.5f*(dd.x + (v.x - mu)*rs*gm.x + be.x);
            o.y = 0.5f*(dd.y + (v.y - mu)*rs*gm.y + be.y);
            o.z = 0.5f*(dd.z + (v.z - mu)*rs*gm.z + be.z);
            o.w = 0.5f*(dd.w + (v.w - mu)*rs*gm.w + be.w);
            *(float4*)&outB[r*FOUTN + col4] = o;
        }
    }
}

extern "C" void kernel_launch(void* const* d_in, const int* in_sizes, int n_in,
                              void* d_out, int out_size)
{
    const float* h     = (const float*)d_in[0];
    const float* adj   = (const float*)d_in[1];
    const float* op    = (const float*)d_in[2];
    const float* W     = (const float*)d_in[3];
    const float* b     = (const float*)d_in[4];
    const float* Wopd  = (const float*)d_in[5];
    const float* bopd  = (const float*)d_in[6];
    const float* Wk    = (const float*)d_in[7];
    const float* aw    = (const float*)d_in[8];
    const float* Wopg  = (const float*)d_in[9];
    const float* bopg  = (const float*)d_in[10];
    const float* gamma = (const float*)d_in[11];
    const float* beta  = (const float*)d_in[12];
    float* out = (float*)d_out;

    const int B = in_sizes[0] / (BN * FINN);   // 2048
    const size_t smem_bytes = SMEM_FLOATS * sizeof(float);

    static bool attr_set = false;
    if (!attr_set) {
        cudaFuncSetAttribute(gin_mma_kernel,
                             cudaFuncAttributeMaxDynamicSharedMemorySize,
                             (int)smem_bytes);
        attr_set = true;
    }

    gin_mma_kernel<<<B, 512, smem_bytes>>>(h, adj, op, W, b, Wopd, bopd,
                                           Wk, aw, Wopg, bopg, gamma, beta, out);
}

// round 9
// speedup vs baseline: 2.9402x; 1.0456x over previous
#include <cuda_runtime.h>
#include <stdint.h>
#include <math.h>

#define BN    64
#define FINN  96
#define FOUTN 128
#define OPDN  48

#define LDH   100   // A-operand pads: LD%32==4 -> conflict-free A-fragment loads
#define LDADJ 68
#define LDSC  68
#define LDOP  52
#define LDW   136   // B-operand pads: LD%32==8 -> conflict-free B-fragment loads
#define EPSV 1e-5f
#define SLOPEV 0.01f

// shared layout (floats). buf1/buf2 are time-multiplexed:
//   phase A: buf1 = W (96x136 tf32), buf2 = Wk (96x136 tf32)
//   phase B: buf1 = Wopd|Wopg (tf32), buf2 = adj (64x68 tf32) | op (64x52 tf32)
//   phase C: buf1 = wa = tf32(whk * a_w) (64x136)
#define OFF_H    0                          // 64x100 = 6400 (tf32)
#define OFF_W1   (OFF_H   + BN*LDH)         // 6400,  13056
#define OFF_W2   (OFF_W1  + 96*LDW)         // 19456, 13056
#define OFF_SUP  (OFF_W2  + 96*LDW)         // 32512, 8704 (fp32: support -> dense)
#define OFF_WHK  (OFF_SUP + BN*LDW)         // 41216, 8704 (fp32: Whk -> hp)
#define OFF_SC   (OFF_WHK + BN*LDW)         // 49920, 4352 (fp32 scores -> attn)
#define OFF_AW   (OFF_SC  + BN*LDSC)        // 54272
#define OFF_B    (OFF_AW  + 128)
#define OFF_BD   (OFF_B   + 128)
#define OFF_BG   (OFF_BD  + 128)
#define OFF_MU   (OFF_BG  + 128)
#define OFF_RS   (OFF_MU  + 64)
#define SMEM_FLOATS (OFF_RS + 64)           // 54912 floats = 219648 B  (< 227KB)

#define OFF_ADJ  OFF_W2                     // 64x68 = 4352
#define OFF_OP   (OFF_W2 + BN*LDADJ)        // 64x52 = 3328 (7680 <= 13056)
#define OFF_WA   OFF_W1                     // 64x136 = 8704 <= 13056

__device__ __forceinline__ uint32_t f2tf(float f) {
    uint32_t u;
    asm("cvt.rna.tf32.f32 %0, %1;" : "=r"(u) : "f"(f));
    return u;
}

__device__ __forceinline__ void mma_tf32(float c[4],
                                         uint32_t a0, uint32_t a1, uint32_t a2, uint32_t a3,
                                         uint32_t b0, uint32_t b1) {
    asm volatile(
        "mma.sync.aligned.m16n8k8.row.col.f32.tf32.tf32.f32 "
        "{%0,%1,%2,%3}, {%4,%5,%6,%7}, {%8,%9}, {%0,%1,%2,%3};"
        : "+f"(c[0]), "+f"(c[1]), "+f"(c[2]), "+f"(c[3])
        : "r"(a0), "r"(a1), "r"(a2), "r"(a3), "r"(b0), "r"(b1));
}

// D[m0..+16, n0..+8*NB] += A[m0..][k] * B[k][n0..];  K = 8*KSTEPS.
// ACVT/BCVT: whether operand is fp32 (needs cvt) or already tf32 bits.
template<int KSTEPS, int NB, bool ACVT, bool BCVT>
__device__ __forceinline__ void gemm_frag(const float* __restrict__ A, int lda,
                                          const float* __restrict__ B, int ldb,
                                          int m0, int n0, int lr, int lc,
                                          float acc[NB][4]) {
    const uint32_t* __restrict__ Au = (const uint32_t*)A;
    const uint32_t* __restrict__ Bu = (const uint32_t*)B;
    #pragma unroll
    for (int ks = 0; ks < KSTEPS; ks++) {
        const int k0 = ks * 8;
        uint32_t a0, a1, a2, a3;
        if (ACVT) {
            a0 = f2tf(A[(m0+lr  )*lda + k0+lc  ]);
            a1 = f2tf(A[(m0+lr+8)*lda + k0+lc  ]);
            a2 = f2tf(A[(m0+lr  )*lda + k0+lc+4]);
            a3 = f2tf(A[(m0+lr+8)*lda + k0+lc+4]);
        } else {
            a0 = Au[(m0+lr  )*lda + k0+lc  ];
            a1 = Au[(m0+lr+8)*lda + k0+lc  ];
            a2 = Au[(m0+lr  )*lda + k0+lc+4];
            a3 = Au[(m0+lr+8)*lda + k0+lc+4];
        }
        #pragma unroll
        for (int nb = 0; nb < NB; nb++) {
            uint32_t b0, b1;
            if (BCVT) {
                b0 = f2tf(B[(k0+lc  )*ldb + n0+nb*8+lr]);
                b1 = f2tf(B[(k0+lc+4)*ldb + n0+nb*8+lr]);
            } else {
                b0 = Bu[(k0+lc  )*ldb + n0+nb*8+lr];
                b1 = Bu[(k0+lc+4)*ldb + n0+nb*8+lr];
            }
            mma_tf32(acc[nb], a0, a1, a2, a3, b0, b1);
        }
    }
}

__device__ __forceinline__ void store_frag4(float* D, int ldd, int m0, int n0,
                                            int lr, int lc, float acc[4][4]) {
    #pragma unroll
    for (int nb = 0; nb < 4; nb++) {
        int c0 = n0 + nb*8 + 2*lc;
        D[(m0+lr  )*ldd + c0  ] = acc[nb][0];
        D[(m0+lr  )*ldd + c0+1] = acc[nb][1];
        D[(m0+lr+8)*ldd + c0  ] = acc[nb][2];
        D[(m0+lr+8)*ldd + c0+1] = acc[nb][3];
    }
}

__global__ void __launch_bounds__(512, 1)
gin_mma2_kernel(const float* __restrict__ g_h, const float* __restrict__ g_adj,
                const float* __restrict__ g_op,
                const float* __restrict__ g_W,  const float* __restrict__ g_b,
                const float* __restrict__ g_Wopd, const float* __restrict__ g_bopd,
                const float* __restrict__ g_Wk, const float* __restrict__ g_aw,
                const float* __restrict__ g_Wopg, const float* __restrict__ g_bopg,
                const float* __restrict__ g_gamma, const float* __restrict__ g_beta,
                float* __restrict__ g_out)
{
    extern __shared__ float smem[];
    float* sh_h   = smem + OFF_H;
    float* sh_w1  = smem + OFF_W1;
    float* sh_w2  = smem + OFF_W2;
    float* sh_sup = smem + OFF_SUP;
    float* sh_whk = smem + OFF_WHK;
    float* sh_sc  = smem + OFF_SC;
    float* sh_aw  = smem + OFF_AW;
    float* sh_b   = smem + OFF_B;
    float* sh_bd  = smem + OFF_BD;
    float* sh_bg  = smem + OFF_BG;
    float* sh_mu  = smem + OFF_MU;
    float* sh_rs  = smem + OFF_RS;
    float* sh_adj = smem + OFF_ADJ;
    float* sh_op  = smem + OFF_OP;
    float* sh_wa  = smem + OFF_WA;

    const int tid  = threadIdx.x;
    const int lane = tid & 31;
    const int w    = tid >> 5;          // 0..15
    const int lr   = lane >> 2;         // 0..7
    const int lc   = lane & 3;          // 0..3
    const int m0   = (w & 3) * 16;      // row block
    const int n0   = (w >> 2) * 32;     // col block (128-col GEMMs)
    const int j0   = (w >> 2) * 16;     // col block (64-col scores)
    const int bb   = blockIdx.x;

    const float* hB   = g_h   + (size_t)bb * BN * FINN;
    const float* adjB = g_adj + (size_t)bb * BN * BN;
    const float* opB  = g_op  + (size_t)bb * BN * OPDN;
    float*       outB = g_out + (size_t)bb * BN * FOUTN;

    // ---- phase A loads: h, W, Wk (pre-converted to tf32 bit patterns) ----
    {
        for (int i = tid; i < BN*24; i += 512) {           // h 64x96
            int r = i / 24, c = i % 24;
            float4 v = ((const float4*)hB)[i];
            uint4 u = { f2tf(v.x), f2tf(v.y), f2tf(v.z), f2tf(v.w) };
            ((uint4*)(sh_h + r*LDH))[c] = u;
        }
        for (int i = tid; i < 96*32; i += 512) {           // W, Wk 96x128
            int r = i / 32, c = i % 32;
            float4 v = ((const float4*)g_W)[i];
            uint4 u = { f2tf(v.x), f2tf(v.y), f2tf(v.z), f2tf(v.w) };
            ((uint4*)(sh_w1 + r*LDW))[c] = u;
            v = ((const float4*)g_Wk)[i];
            uint4 u2 = { f2tf(v.x), f2tf(v.y), f2tf(v.z), f2tf(v.w) };
            ((uint4*)(sh_w2 + r*LDW))[c] = u2;
        }
        if (tid < 128) {
            sh_aw[tid] = g_aw[tid];
            sh_b[tid]  = g_b[tid];
            sh_bd[tid] = g_bopd[tid];
            sh_bg[tid] = g_bopg[tid];
        }
    }
    __syncthreads();

    // ---- fused: support = h@W, Whk = h@Wk (A fragments loaded once) ----
    {
        float acc1[4][4], acc2[4][4];
        #pragma unroll
        for (int a = 0; a < 4; a++)
            #pragma unroll
            for (int t = 0; t < 4; t++) { acc1[a][t] = 0.f; acc2[a][t] = 0.f; }
        const uint32_t* Hu  = (const uint32_t*)sh_h;
        const uint32_t* B1u = (const uint32_t*)sh_w1;
        const uint32_t* B2u = (const uint32_t*)sh_w2;
        #pragma unroll
        for (int ks = 0; ks < 12; ks++) {
            const int k0 = ks * 8;
            uint32_t a0 = Hu[(m0+lr  )*LDH + k0+lc  ];
            uint32_t a1 = Hu[(m0+lr+8)*LDH + k0+lc  ];
            uint32_t a2 = Hu[(m0+lr  )*LDH + k0+lc+4];
            uint32_t a3 = Hu[(m0+lr+8)*LDH + k0+lc+4];
            #pragma unroll
            for (int nb = 0; nb < 4; nb++) {
                uint32_t b0 = B1u[(k0+lc  )*LDW + n0+nb*8+lr];
                uint32_t b1 = B1u[(k0+lc+4)*LDW + n0+nb*8+lr];
                mma_tf32(acc1[nb], a0, a1, a2, a3, b0, b1);
                uint32_t c0 = B2u[(k0+lc  )*LDW + n0+nb*8+lr];
                uint32_t c1 = B2u[(k0+lc+4)*LDW + n0+nb*8+lr];
                mma_tf32(acc2[nb], a0, a1, a2, a3, c0, c1);
            }
        }
        store_frag4(sh_sup, LDW, m0, n0, lr, lc, acc1);
        store_frag4(sh_whk, LDW, m0, n0, lr, lc, acc2);
    }
    __syncthreads();   // done reading W/Wk; sup/whk visible

    // ---- phase B loads: Wopd|Wopg -> w1, adj|op -> w2 (all tf32) ----
    {
        for (int i = tid; i < 48*32; i += 512) {           // Wopd, Wopg 48x128
            int r = i / 32, c = i % 32;
            float4 v = ((const float4*)g_Wopd)[i];
            uint4 u = { f2tf(v.x), f2tf(v.y), f2tf(v.z), f2tf(v.w) };
            ((uint4*)(sh_w1 + r*LDW))[c] = u;
            v = ((const float4*)g_Wopg)[i];
            uint4 u2 = { f2tf(v.x), f2tf(v.y), f2tf(v.z), f2tf(v.w) };
            ((uint4*)(sh_w1 + (48+r)*LDW))[c] = u2;
        }
        for (int i = tid; i < BN*16; i += 512) {           // adj 64x64
            int r = i / 16, c = i % 16;
            float4 v = ((const float4*)adjB)[i];
            uint4 u = { f2tf(v.x), f2tf(v.y), f2tf(v.z), f2tf(v.w) };
            ((uint4*)(sh_adj + r*LDADJ))[c] = u;
        }
        for (int i = tid; i < BN*12; i += 512) {           // op 64x48
            int r = i / 12, c = i % 12;
            float4 v = ((const float4*)opB)[i];
            uint4 u = { f2tf(v.x), f2tf(v.y), f2tf(v.z), f2tf(v.w) };
            ((uint4*)(sh_op + r*LDOP))[c] = u;
        }
    }
    __syncthreads();

    // ---- gates: gd = sigmoid(op@Wop_d + bd), gg = sigmoid(op@Wop_g + bg) ----
    float gdv[4][4], ggv[4][4];
    {
        #pragma unroll
        for (int a = 0; a < 4; a++)
            #pragma unroll
            for (int t = 0; t < 4; t++) { gdv[a][t] = 0.f; ggv[a][t] = 0.f; }
        const uint32_t* Ou  = (const uint32_t*)sh_op;
        const uint32_t* D1u = (const uint32_t*)sh_w1;
        const uint32_t* D2u = (const uint32_t*)(sh_w1 + 48*LDW);
        #pragma unroll
        for (int ks = 0; ks < 6; ks++) {
            const int k0 = ks * 8;
            uint32_t a0 = Ou[(m0+lr  )*LDOP + k0+lc  ];
            uint32_t a1 = Ou[(m0+lr+8)*LDOP + k0+lc  ];
            uint32_t a2 = Ou[(m0+lr  )*LDOP + k0+lc+4];
            uint32_t a3 = Ou[(m0+lr+8)*LDOP + k0+lc+4];
            #pragma unroll
            for (int nb = 0; nb < 4; nb++) {
                uint32_t d0 = D1u[(k0+lc  )*LDW + n0+nb*8+lr];
                uint32_t d1 = D1u[(k0+lc+4)*LDW + n0+nb*8+lr];
                mma_tf32(gdv[nb], a0, a1, a2, a3, d0, d1);
                uint32_t e0 = D2u[(k0+lc  )*LDW + n0+nb*8+lr];
                uint32_t e1 = D2u[(k0+lc+4)*LDW + n0+nb*8+lr];
                mma_tf32(ggv[nb], a0, a1, a2, a3, e0, e1);
            }
        }
        #pragma unroll
        for (int nb = 0; nb < 4; nb++) {
            int cA = n0 + nb*8 + 2*lc, cB = cA + 1;
            gdv[nb][0] = 1.f/(1.f+__expf(-(gdv[nb][0] + sh_bd[cA])));
            gdv[nb][1] = 1.f/(1.f+__expf(-(gdv[nb][1] + sh_bd[cB])));
            gdv[nb][2] = 1.f/(1.f+__expf(-(gdv[nb][2] + sh_bd[cA])));
            gdv[nb][3] = 1.f/(1.f+__expf(-(gdv[nb][3] + sh_bd[cB])));
            ggv[nb][0] = 1.f/(1.f+__expf(-(ggv[nb][0] + sh_bg[cA])));
            ggv[nb][1] = 1.f/(1.f+__expf(-(ggv[nb][1] + sh_bg[cB])));
            ggv[nb][2] = 1.f/(1.f+__expf(-(ggv[nb][2] + sh_bg[cA])));
            ggv[nb][3] = 1.f/(1.f+__expf(-(ggv[nb][3] + sh_bg[cB])));
        }
    }

    // ---- dense = gd * (adj @ support) + support + b (regs) ----
    float dnv[4][4];
    {
        #pragma unroll
        for (int a = 0; a < 4; a++)
            #pragma unroll
            for (int t = 0; t < 4; t++) dnv[a][t] = 0.f;
        gemm_frag<8,4,false,true>(sh_adj, LDADJ, sh_sup, LDW, m0, n0, lr, lc, dnv);
        #pragma unroll
        for (int nb = 0; nb < 4; nb++) {
            int cA = n0 + nb*8 + 2*lc, cB = cA + 1;
            int rA = m0 + lr, rB = m0 + lr + 8;
            dnv[nb][0] = gdv[nb][0]*dnv[nb][0] + sh_sup[rA*LDW + cA] + sh_b[cA];
            dnv[nb][1] = gdv[nb][1]*dnv[nb][1] + sh_sup[rA*LDW + cB] + sh_b[cB];
            dnv[nb][2] = gdv[nb][2]*dnv[nb][2] + sh_sup[rB*LDW + cA] + sh_b[cA];
            dnv[nb][3] = gdv[nb][3]*dnv[nb][3] + sh_sup[rB*LDW + cB] + sh_b[cB];
        }
    }
    __syncthreads();   // all reads of sh_sup & sh_w1 (gates) done

    // ---- dense -> sup; wa = tf32(whk * a_w) -> w1 ----
    store_frag4(sh_sup, LDW, m0, n0, lr, lc, dnv);
    {
        uint32_t* WAu = (uint32_t*)sh_wa;
        for (int i = tid; i < BN*FOUTN; i += 512) {
            int r = i >> 7, c = i & 127;
            WAu[r*LDW + c] = f2tf(sh_whk[r*LDW + c] * sh_aw[c]);
        }
    }
    __syncthreads();

    // ---- scores[i][j] = leaky(sum_m wa[i][m]*whk[j][m]) * adj[i][j] ----
    // B[k=m][n=j] = whk[j][m]: whk stored [j][m] -> rows j, cols m.
    {
        float sc[2][4];
        #pragma unroll
        for (int a = 0; a < 2; a++)
            #pragma unroll
            for (int t = 0; t < 4; t++) sc[a][t] = 0.f;
        const uint32_t* WAu = (const uint32_t*)sh_wa;
        #pragma unroll
        for (int ks = 0; ks < 16; ks++) {
            const int k0 = ks * 8;
            uint32_t a0 = WAu[(m0+lr  )*LDW + k0+lc  ];
            uint32_t a1 = WAu[(m0+lr+8)*LDW + k0+lc  ];
            uint32_t a2 = WAu[(m0+lr  )*LDW + k0+lc+4];
            uint32_t a3 = WAu[(m0+lr+8)*LDW + k0+lc+4];
            #pragma unroll
            for (int nb = 0; nb < 2; nb++) {
                int jrow = j0 + nb*8 + lr;
                uint32_t b0 = f2tf(sh_whk[jrow*LDW + k0+lc  ]);
                uint32_t b1 = f2tf(sh_whk[jrow*LDW + k0+lc+4]);
                mma_tf32(sc[nb], a0, a1, a2, a3, b0, b1);
            }
        }
        const uint32_t* ADJu = (const uint32_t*)sh_adj;  // tf32 bits, still exact 0/1
        #pragma unroll
        for (int nb = 0; nb < 2; nb++) {
            int jA = j0 + nb*8 + 2*lc, jB = jA + 1;
            int iA = m0 + lr, iB = m0 + lr + 8;
            float s;
            s = sc[nb][0]; s = (s >= 0.f) ? s : SLOPEV*s; sh_sc[iA*LDSC + jA] = s * __uint_as_float(ADJu[iA*LDADJ + jA]);
            s = sc[nb][1]; s = (s >= 0.f) ? s : SLOPEV*s; sh_sc[iA*LDSC + jB] = s * __uint_as_float(ADJu[iA*LDADJ + jB]);
            s = sc[nb][2]; s = (s >= 0.f) ? s : SLOPEV*s; sh_sc[iB*LDSC + jA] = s * __uint_as_float(ADJu[iB*LDADJ + jA]);
            s = sc[nb][3]; s = (s >= 0.f) ? s : SLOPEV*s; sh_sc[iB*LDSC + jB] = s * __uint_as_float(ADJu[iB*LDADJ + jB]);
        }
    }
    __syncthreads();

    // ---- softmax over j, 8 threads/row ----
    {
        const int row = tid >> 3;
        const int q   = tid & 7;
        float4 e0 = *(const float4*)&sh_sc[row*LDSC + q*8];
        float4 e1 = *(const float4*)&sh_sc[row*LDSC + q*8 + 4];
        float mx = fmaxf(fmaxf(fmaxf(e0.x,e0.y),fmaxf(e0.z,e0.w)),
                         fmaxf(fmaxf(e1.x,e1.y),fmaxf(e1.z,e1.w)));
        mx = fmaxf(mx, __shfl_xor_sync(0xffffffffu, mx, 1));
        mx = fmaxf(mx, __shfl_xor_sync(0xffffffffu, mx, 2));
        mx = fmaxf(mx, __shfl_xor_sync(0xffffffffu, mx, 4));
        e0.x = __expf(e0.x - mx); e0.y = __expf(e0.y - mx);
        e0.z = __expf(e0.z - mx); e0.w = __expf(e0.w - mx);
        e1.x = __expf(e1.x - mx); e1.y = __expf(e1.y - mx);
        e1.z = __expf(e1.z - mx); e1.w = __expf(e1.w - mx);
        float sum = e0.x+e0.y+e0.z+e0.w+e1.x+e1.y+e1.z+e1.w;
        sum += __shfl_xor_sync(0xffffffffu, sum, 1);
        sum += __shfl_xor_sync(0xffffffffu, sum, 2);
        sum += __shfl_xor_sync(0xffffffffu, sum, 4);
        float inv = 1.f / sum;
        e0.x*=inv; e0.y*=inv; e0.z*=inv; e0.w*=inv;
        e1.x*=inv; e1.y*=inv; e1.z*=inv; e1.w*=inv;
        *(float4*)&sh_sc[row*LDSC + q*8]     = e0;
        *(float4*)&sh_sc[row*LDSC + q*8 + 4] = e1;
    }
    __syncthreads();

    // ---- hp = gg * (attn @ Whk) ----
    {
        float hpv[4][4];
        #pragma unroll
        for (int a = 0; a < 4; a++)
            #pragma unroll
            for (int t = 0; t < 4; t++) hpv[a][t] = 0.f;
        gemm_frag<8,4,true,true>(sh_sc, LDSC, sh_whk, LDW, m0, n0, lr, lc, hpv);
        #pragma unroll
        for (int nb = 0; nb < 4; nb++)
            #pragma unroll
            for (int t = 0; t < 4; t++) hpv[nb][t] *= ggv[nb][t];
        __syncthreads();   // all reads of sh_whk done
        store_frag4(sh_whk, LDW, m0, n0, lr, lc, hpv);
    }
    __syncthreads();

    // ---- LayerNorm stats (8 threads/row) ----
    {
        const int row = tid >> 3;
        const int q   = tid & 7;
        float sum = 0.f, sq = 0.f;
        #pragma unroll
        for (int c = 0; c < 4; c++) {
            float4 v = *(const float4*)&sh_whk[row*LDW + q*16 + c*4];
            sum += v.x+v.y+v.z+v.w;
            sq  += v.x*v.x + v.y*v.y + v.z*v.z + v.w*v.w;
        }
        sum += __shfl_xor_sync(0xffffffffu, sum, 1);
        sum += __shfl_xor_sync(0xffffffffu, sum, 2);
        sum += __shfl_xor_sync(0xffffffffu, sum, 4);
        sq  += __shfl_xor_sync(0xffffffffu, sq, 1);
        sq  += __shfl_xor_sync(0xffffffffu, sq, 2);
        sq  += __shfl_xor_sync(0xffffffffu, sq, 4);
        float mu  = sum * (1.f / FOUTN);
        float var = sq * (1.f / FOUTN) - mu*mu;
        if (q == 0) { sh_mu[row] = mu; sh_rs[row] = rsqrtf(var + EPSV); }
    }
    __syncthreads();

    // ---- combine & write ----
    {
        const int col4 = lane * 4;
        const int r0v  = w * 4;
        float4 gm = *(const float4*)&g_gamma[col4];
        float4 be = *(const float4*)&g_beta[col4];
        #pragma unroll
        for (int ii = 0; ii < 4; ii++) {
            int r = r0v + ii;
            float mu = sh_mu[r], rs = sh_rs[r];
            float4 v  = *(const float4*)&sh_whk[r*LDW + col4];
            float4 dd = *(const float4*)&sh_sup[r*LDW + col4];
            float4 o;
            o.x = 0.5f*(dd.x + (v.x - mu)*rs*gm.x + be.x);
            o.y = 0.5f*(dd.y + (v.y - mu)*rs*gm.y + be.y);
            o.z = 0.5f*(dd.z + (v.z - mu)*rs*gm.z + be.z);
            o.w = 0.5f*(dd.w + (v.w - mu)*rs*gm.w + be.w);
            *(float4*)&outB[r*FOUTN + col4] = o;
        }
    }
}

extern "C" void kernel_launch(void* const* d_in, const int* in_sizes, int n_in,
                              void* d_out, int out_size)
{
    const float* h     = (const float*)d_in[0];
    const float* adj   = (const float*)d_in[1];
    const float* op    = (const float*)d_in[2];
    const float* W     = (const float*)d_in[3];
    const float* b     = (const float*)d_in[4];
    const float* Wopd  = (const float*)d_in[5];
    const float* bopd  = (const float*)d_in[6];
    const float* Wk    = (const float*)d_in[7];
    const float* aw    = (const float*)d_in[8];
    const float* Wopg  = (const float*)d_in[9];
    const float* bopg  = (const float*)d_in[10];
    const float* gamma = (const float*)d_in[11];
    const float* beta  = (const float*)d_in[12];
    float* out = (float*)d_out;

    const int B = in_sizes[0] / (BN * FINN);   // 2048
    const size_t smem_bytes = SMEM_FLOATS * sizeof(float);

    static bool attr_set = false;
    if (!attr_set) {
        cudaFuncSetAttribute(gin_mma2_kernel,
                             cudaFuncAttributeMaxDynamicSharedMemorySize,
                             (int)smem_bytes);
        attr_set = true;
    }

    gin_mma2_kernel<<<B, 512, smem_bytes>>>(h, adj, op, W, b, Wopd, bopd,
                                            Wk, aw, Wopg, bopg, gamma, beta, out);
}